// round 2
// baseline (speedup 1.0000x reference)
#include <cuda_runtime.h>

#define Bx 64
#define Cx 3
#define Hx 384
#define Wx 384
#define PLANE (Hx * Wx)          // 147456
#define PIX4  (Wx / 4)           // 96 quads per row

__global__ __launch_bounds__(256) void affine_kernel(
    const float* __restrict__ imgs,
    const float* __restrict__ theta,
    float* __restrict__ out)
{
    int idx = blockIdx.x * blockDim.x + threadIdx.x;   // one quad of x-pixels
    int xq = idx % PIX4;
    int t  = idx / PIX4;
    int y  = t % Hx;
    int b  = t / Hx;
    if (b >= Bx) return;

    // theta row-major per image: [t00 t01 t02; t10 t11 t12]
    const float* th = theta + b * 6;
    float t00 = __ldg(th + 0), t01 = __ldg(th + 1), t02 = __ldg(th + 2);
    float t10 = __ldg(th + 3), t11 = __ldg(th + 4), t12 = __ldg(th + 5);

    // Folded grid-gen: ix = xv*t00 + yv*t01 + t02 + 191.5, xv = x-191.5, yv = y-191.5
    float yv = (float)y - 191.5f;
    float ix_b = fmaf(yv, t01, t02) + 191.5f;
    float iy_b = fmaf(yv, t11, t12) + 191.5f;

    const float* img = imgs + (size_t)b * (Cx * PLANE);

    float4 r0, r1, r2;
    float* acc0 = &r0.x;
    float* acc1 = &r1.x;
    float* acc2 = &r2.x;

    int xbase = xq * 4;

#pragma unroll
    for (int k = 0; k < 4; k++) {
        float xv = (float)(xbase + k) - 191.5f;
        float ix = fmaf(xv, t00, ix_b);
        float iy = fmaf(xv, t10, iy_b);

        float fx0 = floorf(ix);
        float fy0 = floorf(iy);
        float wx1 = ix - fx0;
        float wy1 = iy - fy0;
        float wx0 = 1.0f - wx1;
        float wy0 = 1.0f - wy1;

        int x0 = (int)fx0;
        int y0 = (int)fy0;
        int x1 = x0 + 1;
        int y1 = y0 + 1;

        // validity -> fold into weights (matches reference's v*valid)
        float vx0 = (x0 >= 0 && x0 < Wx) ? 1.0f : 0.0f;
        float vx1 = (x1 >= 0 && x1 < Wx) ? 1.0f : 0.0f;
        float vy0 = (y0 >= 0 && y0 < Hx) ? 1.0f : 0.0f;
        float vy1 = (y1 >= 0 && y1 < Hx) ? 1.0f : 0.0f;

        float w00 = wx0 * wy0 * vx0 * vy0;
        float w10 = wx1 * wy0 * vx1 * vy0;
        float w01 = wx0 * wy1 * vx0 * vy1;
        float w11 = wx1 * wy1 * vx1 * vy1;

        int xc0 = min(max(x0, 0), Wx - 1);
        int xc1 = min(max(x1, 0), Wx - 1);
        int yc0 = min(max(y0, 0), Hx - 1);
        int yc1 = min(max(y1, 0), Hx - 1);

        int o00 = yc0 * Wx + xc0;
        int o10 = yc0 * Wx + xc1;
        int o01 = yc1 * Wx + xc0;
        int o11 = yc1 * Wx + xc1;

        // Explicit load phase: 12 independent LDGs in flight before any FMA
        float v00c0 = __ldg(img + 0 * PLANE + o00);
        float v10c0 = __ldg(img + 0 * PLANE + o10);
        float v01c0 = __ldg(img + 0 * PLANE + o01);
        float v11c0 = __ldg(img + 0 * PLANE + o11);
        float v00c1 = __ldg(img + 1 * PLANE + o00);
        float v10c1 = __ldg(img + 1 * PLANE + o10);
        float v01c1 = __ldg(img + 1 * PLANE + o01);
        float v11c1 = __ldg(img + 1 * PLANE + o11);
        float v00c2 = __ldg(img + 2 * PLANE + o00);
        float v10c2 = __ldg(img + 2 * PLANE + o10);
        float v01c2 = __ldg(img + 2 * PLANE + o01);
        float v11c2 = __ldg(img + 2 * PLANE + o11);

        acc0[k] = fmaf(w00, v00c0, fmaf(w10, v10c0, fmaf(w01, v01c0, w11 * v11c0)));
        acc1[k] = fmaf(w00, v00c1, fmaf(w10, v10c1, fmaf(w01, v01c1, w11 * v11c1)));
        acc2[k] = fmaf(w00, v00c2, fmaf(w10, v10c2, fmaf(w01, v01c2, w11 * v11c2)));
    }

    size_t obase = ((size_t)(b * Cx) * Hx + y) * Wx + xbase;
    *reinterpret_cast<float4*>(out + obase)             = r0;
    *reinterpret_cast<float4*>(out + obase + PLANE)     = r1;
    *reinterpret_cast<float4*>(out + obase + 2 * PLANE) = r2;
}

extern "C" void kernel_launch(void* const* d_in, const int* in_sizes, int n_in,
                              void* d_out, int out_size)
{
    const float* imgs  = (const float*)d_in[0];
    const float* theta = (const float*)d_in[1];
    float* out = (float*)d_out;

    int total = Bx * Hx * PIX4;               // 2,359,296 threads
    int threads = 256;
    int blocks = (total + threads - 1) / threads;
    affine_kernel<<<blocks, threads>>>(imgs, theta, out);
}